// round 13
// baseline (speedup 1.0000x reference)
#include <cuda_runtime.h>
#include <cuda_bf16.h>
#include <cstdint>

#define N_NODES 50000
#define N_EDGES 800000
#define IN_DIM  128
#define HID     128
#define OUT_DIM 64
#define CAP     96                      // max in-degree (Poisson λ=16 → P(>96) ~ 0)
#define TILES   ((N_NODES + 63) / 64)   // 782 MLP tiles, 9 blocks per tile

// Scratch (device globals — no allocations allowed)
__device__ int   g_idx64;                         // 1 if edge_index is int64
__device__ int   g_cur[N_NODES];                  // cursor == in-degree after fill
__device__ float g_dinv[N_NODES];
__device__ float g_agg[(size_t)N_NODES * IN_DIM]; // aggregated features
__device__ int   g_src[(size_t)N_NODES * CAP];    // bucketed source lists (19.2 MB)
__device__ int   g_ready[TILES];                  // per-tile gather completion count

__device__ __forceinline__ int edge_idx(const void* ei, int i) {
    if (g_idx64) return (int)((const long long*)ei)[i];
    return ((const int*)ei)[i];
}

// ---------------------------------------------------------------------------
// k0: zero cursors + ready flags + dtype detection
// ---------------------------------------------------------------------------
__global__ void k_init(const void* __restrict__ ei) {
    int i = blockIdx.x * blockDim.x + threadIdx.x;
    if (i < N_NODES) g_cur[i] = 0;
    if (i < TILES)   g_ready[i] = 0;
    if (blockIdx.x == 0) {
        __shared__ int s_ok;
        if (threadIdx.x == 0) s_ok = 1;
        __syncthreads();
        long long v = ((const long long*)ei)[threadIdx.x];  // 2KB, in-bounds either way
        if (v < 0 || v >= N_NODES) atomicAnd(&s_ok, 0);
        __syncthreads();
        if (threadIdx.x == 0) g_idx64 = s_ok;
    }
}

// k1: combined count + bucket fill (cursor doubles as in-degree histogram)
__global__ void k_fill(const void* __restrict__ ei) {
    int e = blockIdx.x * blockDim.x + threadIdx.x;
    if (e < N_EDGES) {
        int r = edge_idx(ei, e);
        int c = edge_idx(ei, N_EDGES + e);
        int p = atomicAdd(&g_cur[c], 1);
        if (p < CAP) g_src[(size_t)c * CAP + p] = r;
    }
}

// k2: dinv = rsqrt(deg+1)
__global__ void k_dinv() {
    int i = blockIdx.x * blockDim.x + threadIdx.x;
    if (i < N_NODES) g_dinv[i] = rsqrtf((float)(g_cur[i] + 1));
}

// ---------------------------------------------------------------------------
// k3: fused producer-consumer grid.
//   9 blocks per 64-node tile:
//     role 0..7 (producers): gather 8 nodes each (warp-per-node, proven R11 loop),
//                            then threadfence + release-count g_ready[tile].
//     role 8    (consumer):  spin until g_ready[tile]==8, then proven scalar MLP.
//   Producers precede their consumer in blockIdx order -> in-order dispatch
//   guarantees progress. Gather (LTS-bound) and MLP (FMA-bound) overlap chipwide.
// ---------------------------------------------------------------------------
__global__ void __launch_bounds__(256) k_work(const float* __restrict__ h,
                                              const float* __restrict__ Wg,
                                              const float* __restrict__ bg,
                                              const float* __restrict__ Wf,
                                              const float* __restrict__ bf,
                                              float* __restrict__ out) {
    __shared__ float sA[64 * 128];   // 32 KB (MLP role); idle for producers

    int tile = blockIdx.x / 9;
    int role = blockIdx.x % 9;
    int node0 = tile * 64;
    int tid = threadIdx.x;
    int tx = tid & 31;
    int ty = tid >> 5;

    if (role < 8) {
        // ---------------- producer: gather 8 nodes (warp ty -> one node) -----
        int node = node0 + role * 8 + ty;
        if (node < N_NODES) {
            const float4* h4 = (const float4*)h;
            float dn = __ldg(g_dinv + node);
            float4 acc = __ldg(h4 + (size_t)node * 32 + tx);
            acc.x *= dn; acc.y *= dn; acc.z *= dn; acc.w *= dn;   // self term

            int cnt = __ldg(g_cur + node);
            if (cnt > CAP) cnt = CAP;
            const int* src = g_src + (size_t)node * CAP;
            int p = 0;
            for (; p + 4 <= cnt; p += 4) {
                int r0 = __ldg(src + p + 0), r1 = __ldg(src + p + 1);
                int r2 = __ldg(src + p + 2), r3 = __ldg(src + p + 3);
                float d0 = __ldg(g_dinv + r0), d1 = __ldg(g_dinv + r1);
                float d2 = __ldg(g_dinv + r2), d3 = __ldg(g_dinv + r3);
                float4 v0 = __ldg(h4 + (size_t)r0 * 32 + tx);
                float4 v1 = __ldg(h4 + (size_t)r1 * 32 + tx);
                float4 v2 = __ldg(h4 + (size_t)r2 * 32 + tx);
                float4 v3 = __ldg(h4 + (size_t)r3 * 32 + tx);
                acc.x += v0.x * d0 + v1.x * d1 + v2.x * d2 + v3.x * d3;
                acc.y += v0.y * d0 + v1.y * d1 + v2.y * d2 + v3.y * d3;
                acc.z += v0.z * d0 + v1.z * d1 + v2.z * d2 + v3.z * d3;
                acc.w += v0.w * d0 + v1.w * d1 + v2.w * d2 + v3.w * d3;
            }
            for (; p < cnt; p++) {
                int r = __ldg(src + p);
                float d = __ldg(g_dinv + r);
                float4 v = __ldg(h4 + (size_t)r * 32 + tx);
                acc.x += v.x * d; acc.y += v.y * d; acc.z += v.z * d; acc.w += v.w * d;
            }
            acc.x *= dn; acc.y *= dn; acc.z *= dn; acc.w *= dn;
            ((float4*)g_agg)[(size_t)node * 32 + tx] = acc;
        }
        // release: every thread fences its stores, barrier, one flag increment
        __threadfence();
        __syncthreads();
        if (tid == 0) atomicAdd(&g_ready[tile], 1);
        return;
    }

    // ---------------- consumer: spin, then proven scalar MLP ----------------
    if (tid == 0) {
        while (atomicAdd(&g_ready[tile], 0) < 8) __nanosleep(64);
    }
    __syncthreads();
    __threadfence();   // acquire: order tile loads after flag observation

    // load 64x128 input tile (zero-pad past N)
    for (int i = tid; i < 64 * 32; i += 256) {
        int node = node0 + (i >> 5);
        float4 v = make_float4(0.f, 0.f, 0.f, 0.f);
        if (node < N_NODES) v = ((const float4*)g_agg)[(size_t)node * 32 + (i & 31)];
        ((float4*)sA)[i] = v;
    }
    __syncthreads();

    // ---- phase 1: hid = A @ Wg + bg ----
    float acc[8][4];
    {
        float4 b = __ldg((const float4*)bg + tx);
        #pragma unroll
        for (int i = 0; i < 8; i++) {
            acc[i][0] = b.x; acc[i][1] = b.y; acc[i][2] = b.z; acc[i][3] = b.w;
        }
    }
    #pragma unroll 4
    for (int k = 0; k < 128; k++) {
        float4 w = __ldg((const float4*)(Wg + k * 128) + tx);
        #pragma unroll
        for (int i = 0; i < 8; i++) {
            float a = sA[(8 * ty + i) * 128 + k];
            acc[i][0] += a * w.x;
            acc[i][1] += a * w.y;
            acc[i][2] += a * w.z;
            acc[i][3] += a * w.w;
        }
    }
    __syncthreads();

    // relu -> hidden tile
    #pragma unroll
    for (int i = 0; i < 8; i++) {
        float4 v;
        v.x = fmaxf(acc[i][0], 0.f);
        v.y = fmaxf(acc[i][1], 0.f);
        v.z = fmaxf(acc[i][2], 0.f);
        v.w = fmaxf(acc[i][3], 0.f);
        ((float4*)sA)[(8 * ty + i) * 32 + tx] = v;
    }
    __syncthreads();

    // ---- phase 2: out = hid @ Wf + bf ----
    float o[8][2];
    {
        float2 b = __ldg((const float2*)bf + tx);
        #pragma unroll
        for (int i = 0; i < 8; i++) { o[i][0] = b.x; o[i][1] = b.y; }
    }
    #pragma unroll 4
    for (int k = 0; k < 128; k++) {
        float2 w = __ldg((const float2*)(Wf + k * 64) + tx);
        #pragma unroll
        for (int i = 0; i < 8; i++) {
            float a = sA[(8 * ty + i) * 128 + k];
            o[i][0] += a * w.x;
            o[i][1] += a * w.y;
        }
    }

    #pragma unroll
    for (int i = 0; i < 8; i++) {
        int node = node0 + 8 * ty + i;
        if (node < N_NODES) {
            float2 v; v.x = o[i][0]; v.y = o[i][1];
            ((float2*)out)[(size_t)node * 32 + tx] = v;
        }
    }
}

// ---------------------------------------------------------------------------
// launch — inputs: h[f32 N*128], edge_index[2*E int32-or-int64],
//          W_gcn[f32 128*128], b_gcn[f32 128], W_fc[f32 128*64], b_fc[f32 64]
// output: f32 N*64
// ---------------------------------------------------------------------------
extern "C" void kernel_launch(void* const* d_in, const int* in_sizes, int n_in,
                              void* d_out, int out_size) {
    const float* h  = (const float*)d_in[0];
    const void*  ei = d_in[1];
    const float* Wg = (const float*)d_in[2];
    const float* bg = (const float*)d_in[3];
    const float* Wf = (const float*)d_in[4];
    const float* bf = (const float*)d_in[5];
    float* out = (float*)d_out;

    k_init<<<(N_NODES + 255) / 256, 256>>>(ei);
    k_fill<<<(N_EDGES + 255) / 256, 256>>>(ei);
    k_dinv<<<(N_NODES + 255) / 256, 256>>>();
    k_work<<<TILES * 9, 256>>>(h, Wg, bg, Wf, bf, out);
}